// round 3
// baseline (speedup 1.0000x reference)
#include <cuda_runtime.h>
#include <math.h>

// DualModeSinkhorn — factorized Sinkhorn: Hl = E .* (R ⊗ C).
// E = exp(input) is fixed; 20 iterations only update R (B,8,H,W) and C (B,8,H,W).
// Per half-iteration one fused kernel: 5x5 circular Gaussian conv (separable) of the
// previous marginal + scale update + per-pixel 8x8 matvec producing the next marginal.
// Batches processed in 2 sequential waves of 16 so the per-wave working set (~101 MB)
// stays L2-resident (126 MB) across kernel launches.

#define HW      16384           // 128*128
#define EPSF    1e-8f
#define NB      32
#define BW      16              // batches per wave
#define NWAVES  2
#define NITER   20
#define TPB     256
#define GRID    ((BW * HW) / TPB)   // 1024 blocks

// Scratch (static device globals — no runtime allocation)
__device__ float g_E[(size_t)NB * 64 * HW];   // exp(input), (B, i, j, H, W)
__device__ float g_M[(size_t)NB * 8 * HW];    // row marginal  R_i * sum_j E_ij C_j
__device__ float g_N[(size_t)NB * 8 * HW];    // col marginal  C_j * sum_i E_ij R_i
__device__ float g_R[(size_t)NB * 8 * HW];    // row scale factors
__device__ float g_C[(size_t)NB * 8 * HW];    // col scale factors

// ---------------------------------------------------------------------------
// Shared conv helper: 5x5 circular Gaussian conv of an 8-channel (H,W) plane,
// evaluated at this block's 8x32 pixel tile. Separable: k = ay ⊗ ax exactly
// (ax[d] = col-sums of k, ay[d] = row-sums of k; for the normalized Gaussian
// outer product this reconstructs k to fp32 rounding).
// ---------------------------------------------------------------------------
__device__ __forceinline__ void conv8(
    const float* __restrict__ kern,        // 25 weights (global)
    const float* __restrict__ cin_b,       // marginal base for this batch (8 planes)
    unsigned tid, unsigned tx, unsigned ty, unsigned h0, unsigned w0,
    float s_in[8][12][36], float s_h[8][12][32], float s_k[25],
    float outv[8])
{
    if (tid < 25) s_k[tid] = kern[tid];

    // Load 8 channels of the (12 x 36) halo tile with circular wrap.
    for (unsigned e = tid; e < 8u * 12u * 36u; e += TPB) {
        unsigned ch = e / 432u;
        unsigned r  = e - ch * 432u;
        unsigned hh = r / 36u;
        unsigned ww = r - hh * 36u;
        unsigned gh = (h0 + hh - 2u) & 127u;   // unsigned wrap == mod 128
        unsigned gw = (w0 + ww - 2u) & 127u;
        s_in[ch][hh][ww] = cin_b[(ch << 14) + (gh << 7) + gw];
    }
    __syncthreads();

    float ax[5], ay[5];
#pragma unroll
    for (int d = 0; d < 5; ++d) {
        ax[d] = s_k[d] + s_k[5 + d] + s_k[10 + d] + s_k[15 + d] + s_k[20 + d];
        ay[d] = s_k[5 * d] + s_k[5 * d + 1] + s_k[5 * d + 2] + s_k[5 * d + 3] + s_k[5 * d + 4];
    }

    // Horizontal pass: (12 x 32) per channel.
    for (unsigned e = tid; e < 8u * 12u * 32u; e += TPB) {
        unsigned ch = e / 384u;
        unsigned r  = e - ch * 384u;
        unsigned hh = r >> 5;
        unsigned ww = r & 31u;
        const float* row = &s_in[ch][hh][ww];
        s_h[ch][hh][ww] = ax[0] * row[0] + ax[1] * row[1] + ax[2] * row[2]
                        + ax[3] * row[3] + ax[4] * row[4];
    }
    __syncthreads();

    // Vertical pass at this thread's pixel.
#pragma unroll
    for (int i = 0; i < 8; ++i) {
        outv[i] = ay[0] * s_h[i][ty + 0][tx] + ay[1] * s_h[i][ty + 1][tx]
                + ay[2] * s_h[i][ty + 2][tx] + ay[3] * s_h[i][ty + 3][tx]
                + ay[4] * s_h[i][ty + 4][tx];
    }
}

// ---------------------------------------------------------------------------
// Prologue: E = exp(input); M = row-sums of E (R = C = 1 initially); init R, C.
// ---------------------------------------------------------------------------
__global__ void __launch_bounds__(TPB) k_first(const float* __restrict__ in, int b0)
{
    unsigned idx = blockIdx.x * (unsigned)TPB + threadIdx.x;   // 0 .. BW*HW-1
    unsigned bl  = idx >> 14;
    unsigned p   = idx & (HW - 1);
    unsigned b   = (unsigned)b0 + bl;

    const float* ip = in  + ((size_t)b << 20) + p;   // b*64*HW
    float*       ep = g_E + ((size_t)b << 20) + p;
    unsigned     mb = (b << 17) + p;                 // b*8*HW

#pragma unroll
    for (int i = 0; i < 8; ++i) {
        float m = 0.f;
#pragma unroll
        for (int j = 0; j < 8; ++j) {
            unsigned off = (unsigned)((i << 3) + j) << 14;
            float e = expf(__ldcs(ip + off));        // streamed read-once
            ep[off] = e;
            m += e;
        }
        g_M[mb + ((unsigned)i << 14)] = m;
        g_R[mb + ((unsigned)i << 14)] = 1.f;
        g_C[mb + ((unsigned)i << 14)] = 1.f;
    }
}

// ---------------------------------------------------------------------------
// Fused half-iteration.
// TRANS = 1 (col half): row = conv(M); R /= row+eps; N_j = C_j * sum_i E_ij R_i
// TRANS = 0 (row half): col = conv(N); C /= col+eps; M_i = R_i * sum_j E_ij C_j
// ---------------------------------------------------------------------------
template <int TRANS>
__global__ void __launch_bounds__(TPB) k_step(const float* __restrict__ kern, int b0)
{
    __shared__ float s_in[8][12][36];
    __shared__ float s_h[8][12][32];
    __shared__ float s_k[25];

    unsigned tid = threadIdx.x;
    unsigned tx = tid & 31u, ty = tid >> 5;
    unsigned blk = blockIdx.x;
    unsigned b  = (unsigned)b0 + (blk >> 6);
    unsigned h0 = ((blk >> 2) & 15u) << 3;
    unsigned w0 = (blk & 3u) << 5;
    unsigned p  = ((h0 + ty) << 7) + (w0 + tx);

    const float* convIn = (TRANS ? g_M : g_N) + ((size_t)b << 17);
    float*       vecA   = (TRANS ? g_R : g_C);
    const float* vecB   = (TRANS ? g_C : g_R);
    float*       outM   = (TRANS ? g_N : g_M);

    float cv[8];
    conv8(kern, convIn, tid, tx, ty, h0, w0, s_in, s_h, s_k, cv);

    unsigned mb = (b << 17) + p;
    float av[8];
#pragma unroll
    for (int i = 0; i < 8; ++i) {
        float a = vecA[mb + ((unsigned)i << 14)] / (cv[i] + EPSF);
        av[i] = a;
        vecA[mb + ((unsigned)i << 14)] = a;
    }

    const float* Eb = g_E + ((size_t)b << 20) + p;
    float acc[8] = {0.f, 0.f, 0.f, 0.f, 0.f, 0.f, 0.f, 0.f};
#pragma unroll
    for (int i = 0; i < 8; ++i) {
#pragma unroll
        for (int j = 0; j < 8; ++j) {
            float e = Eb[(unsigned)((i << 3) + j) << 14];
            if (TRANS) acc[j] = fmaf(e, av[i], acc[j]);   // N_j += E_ij * R_i
            else       acc[i] = fmaf(e, av[j], acc[i]);   // M_i += E_ij * C_j
        }
    }
#pragma unroll
    for (int k = 0; k < 8; ++k)
        outM[mb + ((unsigned)k << 14)] = vecB[mb + ((unsigned)k << 14)] * acc[k];
}

// ---------------------------------------------------------------------------
// Epilogue: finish iteration 20's col step, then out = E * R * C + EPS.
// (exp(log(x+eps)) == x+eps to fp32 rounding; tolerance 1e-3.)
// ---------------------------------------------------------------------------
__global__ void __launch_bounds__(TPB) k_epi(const float* __restrict__ kern,
                                             float* __restrict__ out, int b0)
{
    __shared__ float s_in[8][12][36];
    __shared__ float s_h[8][12][32];
    __shared__ float s_k[25];

    unsigned tid = threadIdx.x;
    unsigned tx = tid & 31u, ty = tid >> 5;
    unsigned blk = blockIdx.x;
    unsigned b  = (unsigned)b0 + (blk >> 6);
    unsigned h0 = ((blk >> 2) & 15u) << 3;
    unsigned w0 = (blk & 3u) << 5;
    unsigned p  = ((h0 + ty) << 7) + (w0 + tx);

    float colv[8];
    conv8(kern, g_N + ((size_t)b << 17), tid, tx, ty, h0, w0, s_in, s_h, s_k, colv);

    unsigned mb = (b << 17) + p;
    float cfin[8], rv[8];
#pragma unroll
    for (int j = 0; j < 8; ++j)
        cfin[j] = g_C[mb + ((unsigned)j << 14)] / (colv[j] + EPSF);
#pragma unroll
    for (int i = 0; i < 8; ++i)
        rv[i] = g_R[mb + ((unsigned)i << 14)];

    const float* Eb = g_E + ((size_t)b << 20) + p;
    float*       ob = out + ((size_t)b << 20) + p;
#pragma unroll
    for (int i = 0; i < 8; ++i) {
        float ri = rv[i];
#pragma unroll
        for (int j = 0; j < 8; ++j) {
            unsigned off = (unsigned)((i << 3) + j) << 14;
            float v = fmaf(Eb[off], ri * cfin[j], EPSF);
            __stcs(ob + off, v);                      // streamed write-once
        }
    }
}

// ---------------------------------------------------------------------------
extern "C" void kernel_launch(void* const* d_in, const int* in_sizes, int n_in,
                              void* d_out, int out_size)
{
    (void)out_size;
    const float* in   = (const float*)d_in[0];
    const float* kern = (const float*)d_in[1];
    if (n_in >= 2 && in_sizes[0] == 25) {   // defensive input-order check
        const float* t = in; in = kern; kern = t;
    }
    float* out = (float*)d_out;

    for (int wv = 0; wv < NWAVES; ++wv) {
        int b0 = wv * BW;
        k_first<<<GRID, TPB>>>(in, b0);
        k_step<1><<<GRID, TPB>>>(kern, b0);            // iter 1: col half
        for (int t = 1; t < NITER; ++t) {
            k_step<0><<<GRID, TPB>>>(kern, b0);        // finish iter t col-update, iter t+1 row marginal
            k_step<1><<<GRID, TPB>>>(kern, b0);        // iter t+1 row-update + col marginal
        }
        k_epi<<<GRID, TPB>>>(kern, out, b0);           // finish iter 20 col-update + output
    }
}

// round 5
// speedup vs baseline: 1.0110x; 1.0110x over previous
#include <cuda_runtime.h>
#include <cuda_fp16.h>
#include <math.h>

// DualModeSinkhorn — factorized Sinkhorn: Hl = E .* (R ⊗ C).
// E = exp(input) is fixed; 20 iterations only update R (B,8,H,W) and C (B,8,H,W).
// R3 changes vs R2:
//  * E stored as fp16, pixel-interleaved [b][p][64]: halves traffic, 8x LDG.128/thread.
//  * Per-wave L2 working set now 100 MB (< 126 MB L2) -> steps run from L2.
//  * Epilogue recomputes fp32 E via __expf(input) (output precision unaffected).
//  * __fdividef / __expf fast paths; streaming hints on input/output only.

#define HW      16384           // 128*128
#define EPSF    1e-8f
#define NB      32
#define BW      16              // batches per wave
#define NWAVES  2
#define NITER   20
#define TPB     256
#define GRID    ((BW * HW) / TPB)   // 1024 blocks

// Scratch (static device globals — no runtime allocation)
__device__ __half2 g_Eh[(size_t)NB * HW * 32];  // exp(input) fp16, layout [b][p][i*8+j]
__device__ float   g_M[(size_t)NB * 8 * HW];    // row marginal  R_i * sum_j E_ij C_j
__device__ float   g_N[(size_t)NB * 8 * HW];    // col marginal  C_j * sum_i E_ij R_i
__device__ float   g_R[(size_t)NB * 8 * HW];    // row scale factors
__device__ float   g_C[(size_t)NB * 8 * HW];    // col scale factors

// ---------------------------------------------------------------------------
// 5x5 circular Gaussian conv of the 8-channel (128,128) marginal, evaluated at
// this block's 8x32 tile. Exactly separable: k = ay ⊗ ax (ax = col-sums,
// ay = row-sums of the normalized outer-product kernel).
// ---------------------------------------------------------------------------
__device__ __forceinline__ void conv8(
    const float* __restrict__ kern,
    const float* __restrict__ cin_b,       // marginal base for this batch (8 planes)
    unsigned tid, unsigned tx, unsigned ty, unsigned h0, unsigned w0,
    float s_in[8][12][36], float s_h[8][12][32], float s_k[25],
    float outv[8])
{
    if (tid < 25) s_k[tid] = kern[tid];

    // Load 8 channels of the (12 x 36) halo tile with circular wrap.
    for (unsigned e = tid; e < 8u * 12u * 36u; e += TPB) {
        unsigned ch = e / 432u;
        unsigned r  = e - ch * 432u;
        unsigned hh = r / 36u;
        unsigned ww = r - hh * 36u;
        unsigned gh = (h0 + hh - 2u) & 127u;   // unsigned wrap == mod 128
        unsigned gw = (w0 + ww - 2u) & 127u;
        s_in[ch][hh][ww] = cin_b[(ch << 14) + (gh << 7) + gw];
    }
    __syncthreads();

    float ax[5], ay[5];
#pragma unroll
    for (int d = 0; d < 5; ++d) {
        ax[d] = s_k[d] + s_k[5 + d] + s_k[10 + d] + s_k[15 + d] + s_k[20 + d];
        ay[d] = s_k[5 * d] + s_k[5 * d + 1] + s_k[5 * d + 2] + s_k[5 * d + 3] + s_k[5 * d + 4];
    }

    // Horizontal pass: (12 x 32) per channel.
    for (unsigned e = tid; e < 8u * 12u * 32u; e += TPB) {
        unsigned ch = e / 384u;
        unsigned r  = e - ch * 384u;
        unsigned hh = r >> 5;
        unsigned ww = r & 31u;
        const float* row = &s_in[ch][hh][ww];
        s_h[ch][hh][ww] = ax[0] * row[0] + ax[1] * row[1] + ax[2] * row[2]
                        + ax[3] * row[3] + ax[4] * row[4];
    }
    __syncthreads();

#pragma unroll
    for (int i = 0; i < 8; ++i) {
        outv[i] = ay[0] * s_h[i][ty + 0][tx] + ay[1] * s_h[i][ty + 1][tx]
                + ay[2] * s_h[i][ty + 2][tx] + ay[3] * s_h[i][ty + 3][tx]
                + ay[4] * s_h[i][ty + 4][tx];
    }
}

// ---------------------------------------------------------------------------
// Prologue: E(fp16, interleaved) = exp(input); M = row-sums of E; R = C = 1.
// ---------------------------------------------------------------------------
__global__ void __launch_bounds__(TPB) k_first(const float* __restrict__ in, int b0)
{
    unsigned idx = blockIdx.x * (unsigned)TPB + threadIdx.x;   // 0 .. BW*HW-1
    unsigned bl  = idx >> 14;
    unsigned p   = idx & (HW - 1);
    unsigned b   = (unsigned)b0 + bl;

    const float* ip  = in + ((size_t)b << 20) + p;                    // b*64*HW
    uint4*       ep4 = reinterpret_cast<uint4*>(g_Eh + ((size_t)(b * HW + p) << 5));
    unsigned     mb  = (b << 17) + p;                                  // b*8*HW

#pragma unroll
    for (int i = 0; i < 8; ++i) {
        float m = 0.f;
        __half2 h[4];
#pragma unroll
        for (int jj = 0; jj < 4; ++jj) {
            float e0 = __expf(__ldcs(ip + ((unsigned)(i * 8 + 2 * jj)     << 14)));
            float e1 = __expf(__ldcs(ip + ((unsigned)(i * 8 + 2 * jj + 1) << 14)));
            m += e0 + e1;
            h[jj] = __floats2half2_rn(e0, e1);
        }
        uint4 q;
        q.x = *reinterpret_cast<unsigned*>(&h[0]);
        q.y = *reinterpret_cast<unsigned*>(&h[1]);
        q.z = *reinterpret_cast<unsigned*>(&h[2]);
        q.w = *reinterpret_cast<unsigned*>(&h[3]);
        ep4[i] = q;
        g_M[mb + ((unsigned)i << 14)] = m;
        g_R[mb + ((unsigned)i << 14)] = 1.f;
        g_C[mb + ((unsigned)i << 14)] = 1.f;
    }
}

// ---------------------------------------------------------------------------
// Fused half-iteration.
// TRANS = 1 (col half): row = conv(M); R /= row+eps; N_j = C_j * sum_i E_ij R_i
// TRANS = 0 (row half): col = conv(N); C /= col+eps; M_i = R_i * sum_j E_ij C_j
// ---------------------------------------------------------------------------
template <int TRANS>
__global__ void __launch_bounds__(TPB) k_step(const float* __restrict__ kern, int b0)
{
    __shared__ float s_in[8][12][36];
    __shared__ float s_h[8][12][32];
    __shared__ float s_k[25];

    unsigned tid = threadIdx.x;
    unsigned tx = tid & 31u, ty = tid >> 5;
    unsigned blk = blockIdx.x;
    unsigned b  = (unsigned)b0 + (blk >> 6);
    unsigned h0 = ((blk >> 2) & 15u) << 3;
    unsigned w0 = (blk & 3u) << 5;
    unsigned p  = ((h0 + ty) << 7) + (w0 + tx);

    const float* convIn = (TRANS ? g_M : g_N) + ((size_t)b << 17);
    float*       vecA   = (TRANS ? g_R : g_C);
    const float* vecB   = (TRANS ? g_C : g_R);
    float*       outM   = (TRANS ? g_N : g_M);

    float cv[8];
    conv8(kern, convIn, tid, tx, ty, h0, w0, s_in, s_h, s_k, cv);

    unsigned mb = (b << 17) + p;
    float av[8];
#pragma unroll
    for (int i = 0; i < 8; ++i) {
        float a = __fdividef(vecA[mb + ((unsigned)i << 14)], cv[i] + EPSF);
        av[i] = a;
        vecA[mb + ((unsigned)i << 14)] = a;
    }

    // Per-pixel 8x8 matvec on fp16 E, 8 contiguous LDG.128 per thread.
    const uint4* ep4 = reinterpret_cast<const uint4*>(g_Eh + ((size_t)(b * HW + p) << 5));
    float acc[8] = {0.f, 0.f, 0.f, 0.f, 0.f, 0.f, 0.f, 0.f};
#pragma unroll
    for (int i = 0; i < 8; ++i) {
        uint4 q = ep4[i];
        float2 f0 = __half22float2(*reinterpret_cast<__half2*>(&q.x));
        float2 f1 = __half22float2(*reinterpret_cast<__half2*>(&q.y));
        float2 f2 = __half22float2(*reinterpret_cast<__half2*>(&q.z));
        float2 f3 = __half22float2(*reinterpret_cast<__half2*>(&q.w));
        if (TRANS) {
            float r = av[i];                       // N_j += E_ij * R_i
            acc[0] = fmaf(f0.x, r, acc[0]);  acc[1] = fmaf(f0.y, r, acc[1]);
            acc[2] = fmaf(f1.x, r, acc[2]);  acc[3] = fmaf(f1.y, r, acc[3]);
            acc[4] = fmaf(f2.x, r, acc[4]);  acc[5] = fmaf(f2.y, r, acc[5]);
            acc[6] = fmaf(f3.x, r, acc[6]);  acc[7] = fmaf(f3.y, r, acc[7]);
        } else {                                   // M_i += E_ij * C_j
            float s;
            s  = fmaf(f0.x, av[0], f0.y * av[1]);
            s  = fmaf(f1.x, av[2], fmaf(f1.y, av[3], s));
            s  = fmaf(f2.x, av[4], fmaf(f2.y, av[5], s));
            s  = fmaf(f3.x, av[6], fmaf(f3.y, av[7], s));
            acc[i] = s;
        }
    }
#pragma unroll
    for (int k = 0; k < 8; ++k)
        outM[mb + ((unsigned)k << 14)] = vecB[mb + ((unsigned)k << 14)] * acc[k];
}

// ---------------------------------------------------------------------------
// Epilogue: finish iteration 20's col step; out = exp(input)(fp32) * R * C + EPS.
// (exp(log(x+eps)) == x+eps to fp32 rounding.)
// ---------------------------------------------------------------------------
__global__ void __launch_bounds__(TPB) k_epi(const float* __restrict__ kern,
                                             const float* __restrict__ in,
                                             float* __restrict__ out, int b0)
{
    __shared__ float s_in[8][12][36];
    __shared__ float s_h[8][12][32];
    __shared__ float s_k[25];

    unsigned tid = threadIdx.x;
    unsigned tx = tid & 31u, ty = tid >> 5;
    unsigned blk = blockIdx.x;
    unsigned b  = (unsigned)b0 + (blk >> 6);
    unsigned h0 = ((blk >> 2) & 15u) << 3;
    unsigned w0 = (blk & 3u) << 5;
    unsigned p  = ((h0 + ty) << 7) + (w0 + tx);

    float colv[8];
    conv8(kern, g_N + ((size_t)b << 17), tid, tx, ty, h0, w0, s_in, s_h, s_k, colv);

    unsigned mb = (b << 17) + p;
    float cfin[8], rv[8];
#pragma unroll
    for (int j = 0; j < 8; ++j)
        cfin[j] = __fdividef(g_C[mb + ((unsigned)j << 14)], colv[j] + EPSF);
#pragma unroll
    for (int i = 0; i < 8; ++i)
        rv[i] = g_R[mb + ((unsigned)i << 14)];

    const float* ip = in  + ((size_t)b << 20) + p;
    float*       ob = out + ((size_t)b << 20) + p;
#pragma unroll
    for (int i = 0; i < 8; ++i) {
        float ri = rv[i];
#pragma unroll
        for (int j = 0; j < 8; ++j) {
            unsigned off = (unsigned)((i << 3) + j) << 14;
            float e = __expf(__ldcs(ip + off));      // fp32 E for output precision
            __stcs(ob + off, fmaf(e, ri * cfin[j], EPSF));
        }
    }
}

// ---------------------------------------------------------------------------
extern "C" void kernel_launch(void* const* d_in, const int* in_sizes, int n_in,
                              void* d_out, int out_size)
{
    (void)out_size;
    const float* in   = (const float*)d_in[0];
    const float* kern = (const float*)d_in[1];
    if (n_in >= 2 && in_sizes[0] == 25) {   // defensive input-order check
        const float* t = in; in = kern; kern = t;
    }
    float* out = (float*)d_out;

    for (int wv = 0; wv < NWAVES; ++wv) {
        int b0 = wv * BW;
        k_first<<<GRID, TPB>>>(in, b0);
        k_step<1><<<GRID, TPB>>>(kern, b0);            // iter 1: col half
        for (int t = 1; t < NITER; ++t) {
            k_step<0><<<GRID, TPB>>>(kern, b0);        // finish iter t col-update, next row marginal
            k_step<1><<<GRID, TPB>>>(kern, b0);        // row-update + col marginal
        }
        k_epi<<<GRID, TPB>>>(kern, in, out, b0);       // finish iter 20 col-update + output
    }
}